// round 4
// baseline (speedup 1.0000x reference)
#include <cuda_runtime.h>
#include <cuda_bf16.h>
#include <cstdint>

#define NN   128            // state size
#define NB   2              // batch
#define LL   2048           // sequence length
#define TC   32             // chunk length
#define KC   (LL / TC)      // 64 chunks
#define NG   8              // chunks per group
#define GG   (KC / NG)      // 8 groups

// ---------------- device scratch ----------------
__device__ double g_ATd[NN * NN];     // A transposed, fp64
__device__ float  g_AdT[NN * NN];     // AdT[k*128+j] = Ad[j][k]
__device__ float  g_Bd[NN];
__device__ float  g_AdPT[NN * NN];    // P = Ad^32, transposed layout
__device__ float  g_QT[NN * NN];      // Q = Ad^256, transposed layout
__device__ float  g_locend[NB * KC * NN];   // chunk-local end states (zero init)
__device__ float  g_gle[NB * GG * NN];      // group-local end states
__device__ float  g_gentry[NB * GG * NN];   // group entry states
__device__ float  g_carry[NB * KC * NN];    // chunk entry states
__device__ float  g_states[NB * LL * NN];   // all true states c_t (2 MB)

// ---------------- 1) transpose A to fp64 ----------------
__global__ void k_transpose(const float* __restrict__ A) {
    __shared__ float tile[32][33];
    int bx = blockIdx.x * 32, by = blockIdx.y * 32;
    int x = bx + threadIdx.x;
    for (int r = threadIdx.y; r < 32; r += 8)
        tile[r][threadIdx.x] = A[(by + r) * NN + x];
    __syncthreads();
    int xo = by + threadIdx.x;
    for (int r = threadIdx.y; r < 32; r += 8)
        g_ATd[(bx + r) * NN + xo] = (double)tile[threadIdx.x][r];
}

// ---------------- 2) discretize (fp64 forward substitution, 1 bar/step) -------
__global__ void __launch_bounds__(NN) k_disc(const float* __restrict__ B) {
    __shared__ double dinv[NN];
    __shared__ double xsh[2];
    int c = blockIdx.x, i = threadIdx.x;

    dinv[i] = 1.0 / (1.0 - 0.5 * g_ATd[i * NN + i]);

    double ri;
    if (c < NN) ri = (i == c ? 1.0 : 0.0) + 0.5 * g_ATd[c * NN + i];
    else        ri = (double)B[i];

    double a_next = 0.5 * g_ATd[0 * NN + i];
    __syncthreads();

    for (int j = 0; j < NN; j++) {
        double aj = a_next;
        if (j + 1 < NN) a_next = 0.5 * g_ATd[(j + 1) * NN + i];
        if (i == j) xsh[j & 1] = ri * dinv[j];
        __syncthreads();
        double x = xsh[j & 1];
        if (i > j)       ri = fma(aj, x, ri);
        else if (i == j) ri = x;
    }
    if (c < NN) g_AdT[c * NN + i] = (float)ri;
    else        g_Bd[i] = (float)ri;
}

// ---------------- serial-matvec primitive (512 threads, 1 bar/step) -----------
// tid = j*? no: j = tid>>2, p = tid&3. Each thread holds a 32-row slice of the
// (transposed-layout) matrix in registers; state lives in double-buffered shared.
__device__ __forceinline__ void load_rows(float* ap, const float* __restrict__ M,
                                          int j, int p) {
#pragma unroll
    for (int k = 0; k < 32; k++) ap[k] = M[(p * 32 + k) * NN + j];
}

__device__ __forceinline__ float mv_step(const float* __restrict__ ap,
                                         const float* __restrict__ curbuf, int p) {
    const float4* c4 = (const float4*)curbuf + p * 8;
    float a0 = 0.f, a1 = 0.f, a2 = 0.f, a3 = 0.f;
#pragma unroll
    for (int k4 = 0; k4 < 8; k4++) {
        float4 cv = c4[k4];
        a0 = fmaf(ap[4 * k4 + 0], cv.x, a0);
        a1 = fmaf(ap[4 * k4 + 1], cv.y, a1);
        a2 = fmaf(ap[4 * k4 + 2], cv.z, a2);
        a3 = fmaf(ap[4 * k4 + 3], cv.w, a3);
    }
    float s = (a0 + a1) + (a2 + a3);
    s += __shfl_xor_sync(0xffffffffu, s, 1);
    s += __shfl_xor_sync(0xffffffffu, s, 2);
    return s;   // full dot valid at p==0
}

// ---------------- 3) chunk locals (128 blk) + P=Ad^32 columns (128 blk) -------
__global__ void __launch_bounds__(512) k_chain(const float* __restrict__ f) {
    __shared__ float cur[2][NN];
    __shared__ float fsh[TC];
    int tid = threadIdx.x, j = tid >> 2, p = tid & 3;
    float ap[32]; load_rows(ap, g_AdT, j, p);

    int blk = blockIdx.x;
    if (blk < 128) {
        int b = blk >> 6, ch = blk & 63;
        float bd = (p == 0) ? g_Bd[j] : 0.f;
        if (tid < TC) fsh[tid] = f[b * LL + ch * TC + tid];
        if (p == 0) cur[0][j] = 0.f;
        __syncthreads();
        float nc = 0.f;
        for (int s = 0; s < TC; s++) {
            float d = mv_step(ap, cur[s & 1], p);
            if (p == 0) { nc = fmaf(bd, fsh[s], d); cur[(s + 1) & 1][j] = nc; }
            __syncthreads();
        }
        if (p == 0) g_locend[(b * KC + ch) * NN + j] = nc;
    } else {
        int j0 = blk - 128;
        if (p == 0) cur[0][j] = (j == j0) ? 1.f : 0.f;
        __syncthreads();
        float nc = 0.f;
        for (int s = 0; s < TC; s++) {
            float d = mv_step(ap, cur[s & 1], p);
            if (p == 0) { nc = d; cur[(s + 1) & 1][j] = nc; }
            __syncthreads();
        }
        if (p == 0) g_AdPT[j0 * NN + j] = nc;
    }
}

// ---------------- 4a) Q=P^8 columns (128 blk) + group-local scans (16 blk) ----
__global__ void __launch_bounds__(512) k_powgroup() {
    __shared__ float cur[2][NN];
    __shared__ float add[NG][NN];
    int tid = threadIdx.x, j = tid >> 2, p = tid & 3;
    float ap[32]; load_rows(ap, g_AdPT, j, p);

    int blk = blockIdx.x;
    if (blk < 128) {                       // column j0 of Q = P^8
        int j0 = blk;
        if (p == 0) cur[0][j] = (j == j0) ? 1.f : 0.f;
        __syncthreads();
        float nc = 0.f;
        for (int s = 0; s < NG; s++) {
            float d = mv_step(ap, cur[s & 1], p);
            if (p == 0) { nc = d; cur[(s + 1) & 1][j] = nc; }
            __syncthreads();
        }
        if (p == 0) g_QT[j0 * NN + j] = nc;
    } else {                               // group-local scan: L <- P L + locend
        int gb = blk - 128;                // 0..15
        int b = gb >> 3, g = gb & 7;
        for (int idx = tid; idx < NG * NN; idx += 512)
            ((float*)add)[idx] = g_locend[(b * KC + g * NG) * NN + idx];
        if (p == 0) cur[0][j] = 0.f;
        __syncthreads();
        float nc = 0.f;
        for (int s = 0; s < NG; s++) {
            float d = mv_step(ap, cur[s & 1], p);
            if (p == 0) { nc = d + add[s][j]; cur[(s + 1) & 1][j] = nc; }
            __syncthreads();
        }
        if (p == 0) g_gle[(b * GG + g) * NN + j] = nc;
    }
}

// ---------------- 4b) group-entry scan with Q (2 blocks, depth 8) -------------
__global__ void __launch_bounds__(512) k_carryB(float* __restrict__ cfin) {
    __shared__ float cur[2][NN];
    __shared__ float add[GG][NN];
    int tid = threadIdx.x, j = tid >> 2, p = tid & 3, b = blockIdx.x;
    float ap[32]; load_rows(ap, g_QT, j, p);

    for (int idx = tid; idx < GG * NN; idx += 512)
        ((float*)add)[idx] = g_gle[b * GG * NN + idx];
    if (p == 0) { cur[0][j] = 0.f; g_gentry[(b * GG + 0) * NN + j] = 0.f; }
    __syncthreads();
    for (int g = 1; g <= GG; g++) {
        float d = mv_step(ap, cur[(g - 1) & 1], p);
        if (p == 0) {
            float nc = d + add[g - 1][j];
            cur[g & 1][j] = nc;
            if (g < GG)            g_gentry[(b * GG + g) * NN + j] = nc;
            else if (cfin)         cfin[b * NN + j] = nc;     // c_final
        }
        __syncthreads();
    }
}

// ---------------- 4c) chunk carries within each group (16 blocks, depth 7) ----
__global__ void __launch_bounds__(512) k_carryC() {
    __shared__ float cur[2][NN];
    __shared__ float add[NG][NN];
    int tid = threadIdx.x, j = tid >> 2, p = tid & 3;
    int b = blockIdx.x >> 3, g = blockIdx.x & 7;
    float ap[32]; load_rows(ap, g_AdPT, j, p);

    for (int idx = tid; idx < (NG - 1) * NN; idx += 512)
        ((float*)add)[idx] = g_locend[(b * KC + g * NG) * NN + idx];
    if (p == 0) {
        float e = g_gentry[(b * GG + g) * NN + j];
        cur[0][j] = e;
        g_carry[(b * KC + g * NG) * NN + j] = e;
    }
    __syncthreads();
    for (int c = 1; c < NG; c++) {
        float d = mv_step(ap, cur[(c - 1) & 1], p);
        if (p == 0) {
            float nc = d + add[c - 1][j];
            cur[c & 1][j] = nc;
            g_carry[(b * KC + g * NG + c) * NN + j] = nc;
        }
        __syncthreads();
    }
}

// ---------------- 5) replay recurrence with true carry, store states ----------
__global__ void __launch_bounds__(512) k_states(const float* __restrict__ f) {
    __shared__ float cur[2][NN];
    __shared__ float fsh[TC];
    int tid = threadIdx.x, j = tid >> 2, p = tid & 3;
    int ch = blockIdx.x, b = blockIdx.y;
    float ap[32]; load_rows(ap, g_AdT, j, p);
    float bd = (p == 0) ? g_Bd[j] : 0.f;

    if (tid < TC) fsh[tid] = f[b * LL + ch * TC + tid];
    if (p == 0) cur[0][j] = g_carry[(b * KC + ch) * NN + j];
    float* sp = g_states + ((size_t)(b * LL + ch * TC)) * NN;
    __syncthreads();

    for (int s = 0; s < TC; s++) {
        float d = mv_step(ap, cur[s & 1], p);
        if (p == 0) {
            float nc = fmaf(bd, fsh[s], d);
            cur[(s + 1) & 1][j] = nc;
            sp[(size_t)s * NN + j] = nc;
        }
        __syncthreads();
    }
}

// ---------------- 6) streaming expansion: y[b,t,n,k] = C[n]*c_t[k] + D*f_t ----
__global__ void __launch_bounds__(256) k_expand(const float* __restrict__ f,
                                                const float* __restrict__ C,
                                                const float* __restrict__ D,
                                                float* __restrict__ y) {
    __shared__ float cs[NN];
    __shared__ float Csh[NN];
    int tid = threadIdx.x;
    int t = blockIdx.x, b = blockIdx.y;

    if (tid < NN) {
        cs[tid]  = g_states[((size_t)(b * LL + t)) * NN + tid];
        Csh[tid] = C[tid];
    }
    float df = D[0] * f[b * LL + t];
    __syncthreads();

    float4* out = (float4*)(y + ((size_t)(b * LL + t)) * (NN * NN));
    float4 cv = ((const float4*)cs)[tid & 31];
    int n0 = tid >> 5;
#pragma unroll
    for (int it = 0; it < 16; it++) {
        float cn = Csh[n0 + 8 * it];
        float4 o;
        o.x = fmaf(cn, cv.x, df);
        o.y = fmaf(cn, cv.y, df);
        o.z = fmaf(cn, cv.z, df);
        o.w = fmaf(cn, cv.w, df);
        out[tid + 256 * it] = o;
    }
}

// ---------------- launcher ----------------------------------------------------
extern "C" void kernel_launch(void* const* d_in, const int* in_sizes, int n_in,
                              void* d_out, int out_size) {
    const float* f = (const float*)d_in[0];
    const float* A = (const float*)d_in[1];
    const float* B = (const float*)d_in[2];
    const float* C = (const float*)d_in[3];
    const float* D = (const float*)d_in[4];

    const long long Y_ELEMS = (long long)NB * LL * NN * NN;   // 67,108,864
    long long off = (long long)out_size - Y_ELEMS;
    if (off < 0) off = 0;
    float* y    = (float*)d_out + off;
    float* cfin = (off >= NB * NN) ? (float*)d_out : nullptr;

    k_transpose<<<dim3(4, 4), dim3(32, 8)>>>(A);
    k_disc<<<NN + 1, NN>>>(B);
    k_chain<<<256, 512>>>(f);
    k_powgroup<<<144, 512>>>();
    k_carryB<<<NB, 512>>>(cfin);
    k_carryC<<<16, 512>>>();
    k_states<<<dim3(KC, NB), 512>>>(f);
    k_expand<<<dim3(LL, NB), 256>>>(f, C, D, y);
}

// round 5
// speedup vs baseline: 2.0441x; 2.0441x over previous
#include <cuda_runtime.h>
#include <cuda_bf16.h>
#include <cstdint>

#define NN   128            // state size
#define NB   2              // batch
#define LL   2048           // sequence length
#define TC   16             // chunk length
#define KC   (LL / TC)      // 128 chunks per batch
#define NG   8              // chunks per group
#define GG   (KC / NG)      // 16 groups per batch

// ---------------- device scratch ----------------
__device__ double g_ATd[NN * NN];     // A transposed, fp64
__device__ float  g_AdT[NN * NN];     // AdT[k*128+j] = Ad[j][k]
__device__ float  g_Bd[NN];
__device__ float  g_PT[NN * NN];      // P = Ad^16, transposed layout
__device__ float  g_QT[NN * NN];      // Q = P^8 = Ad^128, transposed layout
__device__ float  g_locend[NB * KC * NN];   // chunk-local end states
__device__ float  g_gle[NB * GG * NN];      // group-local end states
__device__ float  g_gentry[NB * GG * NN];   // group entry states
__device__ float  g_carry[NB * KC * NN];    // chunk entry states
__device__ float  g_states[NB * LL * NN];   // all true states c_t (2 MB)

// ---------------- 1) transpose A to fp64 ----------------
__global__ void k_transpose(const float* __restrict__ A) {
    __shared__ float tile[32][33];
    int bx = blockIdx.x * 32, by = blockIdx.y * 32;
    int x = bx + threadIdx.x;
    for (int r = threadIdx.y; r < 32; r += 8)
        tile[r][threadIdx.x] = A[(by + r) * NN + x];
    __syncthreads();
    int xo = by + threadIdx.x;
    for (int r = threadIdx.y; r < 32; r += 8)
        g_ATd[(bx + r) * NN + xo] = (double)tile[threadIdx.x][r];
}

// ---------------- 2) discretize (fp64 forward substitution, 1 bar/step) -------
__global__ void __launch_bounds__(NN) k_disc(const float* __restrict__ B) {
    __shared__ double dinv[NN];
    __shared__ double xsh[2];
    int c = blockIdx.x, i = threadIdx.x;

    dinv[i] = 1.0 / (1.0 - 0.5 * g_ATd[i * NN + i]);

    double ri;
    if (c < NN) ri = (i == c ? 1.0 : 0.0) + 0.5 * g_ATd[c * NN + i];
    else        ri = (double)B[i];

    double a_next = 0.5 * g_ATd[0 * NN + i];
    __syncthreads();

    for (int j = 0; j < NN; j++) {
        double aj = a_next;
        if (j + 1 < NN) a_next = 0.5 * g_ATd[(j + 1) * NN + i];
        if (i == j) xsh[j & 1] = ri * dinv[j];
        __syncthreads();
        double x = xsh[j & 1];
        if (i > j)       ri = fma(aj, x, ri);
        else if (i == j) ri = x;
    }
    if (c < NN) g_AdT[c * NN + i] = (float)ri;   // Ad[i][c] at AdT[c*128+i]
    else        g_Bd[i] = (float)ri;
}

// ---------------- canonical serial-matvec pieces (128 thr, 1 bar/step) --------
// Thread j holds matrix row j in registers (from transposed layout M[k*128+j]).
__device__ __forceinline__ void load_row(float* ad, const float* __restrict__ M,
                                         int j) {
#pragma unroll
    for (int k = 0; k < NN; k++) ad[k] = M[k * NN + j];
}

__device__ __forceinline__ float dot128(const float* __restrict__ ad,
                                        const float* __restrict__ csh) {
    const float4* c4 = (const float4*)csh;
    float a0 = 0.f, a1 = 0.f, a2 = 0.f, a3 = 0.f;
#pragma unroll
    for (int k4 = 0; k4 < 32; k4++) {
        float4 cv = c4[k4];
        a0 = fmaf(ad[4 * k4 + 0], cv.x, a0);
        a1 = fmaf(ad[4 * k4 + 1], cv.y, a1);
        a2 = fmaf(ad[4 * k4 + 2], cv.z, a2);
        a3 = fmaf(ad[4 * k4 + 3], cv.w, a3);
    }
    return (a0 + a1) + (a2 + a3);
}

// ---------------- 3) chunk locals (256 blk) + P=Ad^16 columns (128 blk) -------
__global__ void __launch_bounds__(NN) k_chain(const float* __restrict__ f) {
    __shared__ float cur[2][NN];
    __shared__ float fsh[TC];
    int j = threadIdx.x;
    float ad[NN]; load_row(ad, g_AdT, j);

    int blk = blockIdx.x;
    if (blk < NB * KC) {                    // local scan from zero
        int b = blk >> 7, ch = blk & (KC - 1);
        float bd = g_Bd[j];
        if (j < TC) fsh[j] = f[b * LL + ch * TC + j];
        cur[0][j] = 0.f;
        __syncthreads();
        float nc = 0.f;
        for (int s = 0; s < TC; s++) {
            float d = dot128(ad, cur[s & 1]);
            nc = fmaf(bd, fsh[s], d);
            cur[(s + 1) & 1][j] = nc;
            __syncthreads();
        }
        g_locend[(b * KC + ch) * NN + j] = nc;
    } else {                                 // column j0 of P = Ad^16
        int j0 = blk - NB * KC;
        cur[0][j] = (j == j0) ? 1.f : 0.f;
        __syncthreads();
        float nc = 0.f;
        for (int s = 0; s < TC; s++) {
            nc = dot128(ad, cur[s & 1]);
            cur[(s + 1) & 1][j] = nc;
            __syncthreads();
        }
        g_PT[j0 * NN + j] = nc;              // P[j][j0]
    }
}

// ---------------- 4a) Q=P^8 columns (128 blk) + group-local scans (32 blk) ----
__global__ void __launch_bounds__(NN) k_powgroup() {
    __shared__ float cur[2][NN];
    __shared__ float add[NG][NN];
    int j = threadIdx.x;
    float ap[NN]; load_row(ap, g_PT, j);

    int blk = blockIdx.x;
    if (blk < NN) {                          // column j0 of Q = P^8
        int j0 = blk;
        cur[0][j] = (j == j0) ? 1.f : 0.f;
        __syncthreads();
        float nc = 0.f;
        for (int s = 0; s < NG; s++) {
            nc = dot128(ap, cur[s & 1]);
            cur[(s + 1) & 1][j] = nc;
            __syncthreads();
        }
        g_QT[j0 * NN + j] = nc;
    } else {                                 // group-local: z <- P z + locend
        int gb = blk - NN;                   // 0..31
        int b = gb >> 4, g = gb & (GG - 1);
        for (int s = 0; s < NG; s++)
            add[s][j] = g_locend[(b * KC + g * NG + s) * NN + j];
        cur[0][j] = 0.f;
        __syncthreads();
        float nc = 0.f;
        for (int s = 0; s < NG; s++) {
            float d = dot128(ap, cur[s & 1]);
            nc = d + add[s][j];
            cur[(s + 1) & 1][j] = nc;
            __syncthreads();
        }
        g_gle[(b * GG + g) * NN + j] = nc;
    }
}

// ---------------- 4b) group-entry scan with Q (2 blocks, depth 16) ------------
__global__ void __launch_bounds__(NN) k_carryB(float* __restrict__ cfin) {
    __shared__ float cur[2][NN];
    __shared__ float add[GG][NN];
    int j = threadIdx.x, b = blockIdx.x;
    float aq[NN]; load_row(aq, g_QT, j);

    for (int g = 0; g < GG; g++)
        add[g][j] = g_gle[(b * GG + g) * NN + j];
    cur[0][j] = 0.f;
    g_gentry[(b * GG + 0) * NN + j] = 0.f;
    __syncthreads();

    for (int g = 1; g <= GG; g++) {
        float d = dot128(aq, cur[(g - 1) & 1]);
        float nc = d + add[g - 1][j];
        cur[g & 1][j] = nc;
        if (g < GG)   g_gentry[(b * GG + g) * NN + j] = nc;
        else if (cfin) cfin[b * NN + j] = nc;     // c_final
        __syncthreads();
    }
}

// ---------------- 4c) chunk carries within each group (32 blocks, depth 7) ----
__global__ void __launch_bounds__(NN) k_carryC() {
    __shared__ float cur[2][NN];
    __shared__ float add[NG][NN];
    int j = threadIdx.x;
    int b = blockIdx.x >> 4, g = blockIdx.x & (GG - 1);
    float ap[NN]; load_row(ap, g_PT, j);

    for (int s = 0; s < NG - 1; s++)
        add[s][j] = g_locend[(b * KC + g * NG + s) * NN + j];
    float e = g_gentry[(b * GG + g) * NN + j];
    cur[0][j] = e;
    g_carry[(b * KC + g * NG) * NN + j] = e;
    __syncthreads();

    for (int c = 1; c < NG; c++) {
        float d = dot128(ap, cur[(c - 1) & 1]);
        float nc = d + add[c - 1][j];
        cur[c & 1][j] = nc;
        g_carry[(b * KC + g * NG + c) * NN + j] = nc;
        __syncthreads();
    }
}

// ---------------- 5) replay recurrence with true carry, store states ----------
__global__ void __launch_bounds__(NN) k_states(const float* __restrict__ f) {
    __shared__ float cur[2][NN];
    __shared__ float fsh[TC];
    int j = threadIdx.x;
    int ch = blockIdx.x, b = blockIdx.y;
    float ad[NN]; load_row(ad, g_AdT, j);
    float bd = g_Bd[j];

    if (j < TC) fsh[j] = f[b * LL + ch * TC + j];
    cur[0][j] = g_carry[(b * KC + ch) * NN + j];
    float* sp = g_states + ((size_t)(b * LL + ch * TC)) * NN;
    __syncthreads();

    for (int s = 0; s < TC; s++) {
        float d = dot128(ad, cur[s & 1]);
        float nc = fmaf(bd, fsh[s], d);
        cur[(s + 1) & 1][j] = nc;
        sp[(size_t)s * NN + j] = nc;        // coalesced, off critical path
        __syncthreads();
    }
}

// ---------------- 6) streaming expansion: y[b,t,n,k] = C[n]*c_t[k] + D*f_t ----
__global__ void __launch_bounds__(256) k_expand(const float* __restrict__ f,
                                                const float* __restrict__ C,
                                                const float* __restrict__ D,
                                                float* __restrict__ y) {
    __shared__ float cs[NN];
    __shared__ float Csh[NN];
    int tid = threadIdx.x;
    int t = blockIdx.x, b = blockIdx.y;

    if (tid < NN) {
        cs[tid]  = g_states[((size_t)(b * LL + t)) * NN + tid];
        Csh[tid] = C[tid];
    }
    float df = D[0] * f[b * LL + t];
    __syncthreads();

    float4* out = (float4*)(y + ((size_t)(b * LL + t)) * (NN * NN));
    float4 cv = ((const float4*)cs)[tid & 31];
    int n0 = tid >> 5;
#pragma unroll
    for (int it = 0; it < 16; it++) {
        float cn = Csh[n0 + 8 * it];
        float4 o;
        o.x = fmaf(cn, cv.x, df);
        o.y = fmaf(cn, cv.y, df);
        o.z = fmaf(cn, cv.z, df);
        o.w = fmaf(cn, cv.w, df);
        out[tid + 256 * it] = o;
    }
}

// ---------------- launcher ----------------------------------------------------
extern "C" void kernel_launch(void* const* d_in, const int* in_sizes, int n_in,
                              void* d_out, int out_size) {
    const float* f = (const float*)d_in[0];
    const float* A = (const float*)d_in[1];
    const float* B = (const float*)d_in[2];
    const float* C = (const float*)d_in[3];
    const float* D = (const float*)d_in[4];

    const long long Y_ELEMS = (long long)NB * LL * NN * NN;   // 67,108,864
    long long off = (long long)out_size - Y_ELEMS;
    if (off < 0) off = 0;
    float* y    = (float*)d_out + off;
    float* cfin = (off >= NB * NN) ? (float*)d_out : nullptr;

    k_transpose<<<dim3(4, 4), dim3(32, 8)>>>(A);
    k_disc<<<NN + 1, NN>>>(B);
    k_chain<<<NB * KC + NN, NN>>>(f);        // 384 blocks
    k_powgroup<<<NN + NB * GG, NN>>>();      // 160 blocks
    k_carryB<<<NB, NN>>>(cfin);
    k_carryC<<<NB * GG, NN>>>();             // 32 blocks
    k_states<<<dim3(KC, NB), NN>>>(f);
    k_expand<<<dim3(LL, NB), 256>>>(f, C, D, y);
}